// round 1
// baseline (speedup 1.0000x reference)
#include <cuda_runtime.h>
#include <math.h>

#define T_   4096
#define H_   2048
#define E_   32
#define KTOP 4
#define I_   1408
#define R_   128
#define SI_  2816
#define TK_  (T_*KTOP)

// ---------------- scratch (device globals; no allocation allowed) ----------------
__device__ int   g_cnt[E_];
__device__ int   g_off[E_+1];
__device__ int   g_tok2d[E_*T_];
__device__ float g_w2d[E_*T_];
__device__ int   g_tokslot[TK_];
__device__ float g_wslot[TK_];
__device__ int   g_slot_of[TK_];
__device__ int   g_tokc[T_];
__device__ float g_rg[T_*R_];
__device__ float g_ru[T_*R_];
__device__ float g_srg[T_*R_];
__device__ float g_sru[T_*R_];
__device__ float g_tg[TK_*R_];
__device__ float g_tu[TK_*R_];
__device__ float g_h[(size_t)TK_*I_];
__device__ float g_rd[TK_*R_];
__device__ float g_td[TK_*R_];
__device__ float g_sh[(size_t)T_*SI_];
__device__ float g_st1[T_*R_];
__device__ float g_st2[T_*R_];
__device__ float g_srd[T_*R_];
__device__ float g_std[T_*R_];
__device__ float g_eout[(size_t)TK_*H_];

// ---------------- init ----------------
__global__ void init_kernel() {
    int i = blockIdx.x*256 + threadIdx.x;
    if (i < E_) g_cnt[i] = 0;
    if (i < T_) g_tokc[i] = 0;
}

// ---------------- gate: fp32 logits, softmax, top-4, per-expert staging ----------------
__global__ void gate_kernel(const float* __restrict__ x, const float* __restrict__ gw) {
    __shared__ float xs[H_];
    __shared__ float lg[E_];
    int t = blockIdx.x;
    const float* xr = x + (size_t)t*H_;
    for (int i = threadIdx.x; i < H_; i += 256) xs[i] = xr[i];
    __syncthreads();
    int warp = threadIdx.x >> 5, lane = threadIdx.x & 31;
    for (int e = warp; e < E_; e += 8) {
        const float* w = gw + (size_t)e*H_;
        float s = 0.f;
        for (int i = lane; i < H_; i += 32) s += xs[i]*w[i];
        #pragma unroll
        for (int o = 16; o; o >>= 1) s += __shfl_xor_sync(0xffffffffu, s, o);
        if (lane == 0) lg[e] = s;
    }
    __syncthreads();
    if (threadIdx.x == 0) {
        float mx = lg[0];
        for (int e = 1; e < E_; e++) mx = fmaxf(mx, lg[e]);
        float p[E_]; float sum = 0.f;
        for (int e = 0; e < E_; e++) { p[e] = expf(lg[e]-mx); sum += p[e]; }
        float inv = 1.f/sum;
        bool taken[E_];
        for (int e = 0; e < E_; e++) taken[e] = false;
        int idx[KTOP]; float w4[KTOP]; float ws = 0.f;
        for (int k = 0; k < KTOP; k++) {
            int best = 0; float bv = -1.f;
            for (int e = 0; e < E_; e++)
                if (!taken[e] && p[e] > bv) { bv = p[e]; best = e; }
            taken[best] = true; idx[k] = best; w4[k] = bv*inv; ws += w4[k];
        }
        float rn = 1.f/(ws + 1e-20f);
        for (int k = 0; k < KTOP; k++) {
            int e = idx[k];
            int pos = atomicAdd(&g_cnt[e], 1);
            g_tok2d[e*T_ + pos] = t;
            g_w2d [e*T_ + pos] = w4[k]*rn;
        }
    }
}

// ---------------- exclusive scan over 32 counts ----------------
__global__ void scan_kernel() {
    if (threadIdx.x == 0 && blockIdx.x == 0) {
        int a = 0;
        for (int e = 0; e < E_; e++) { g_off[e] = a; a += g_cnt[e]; }
        g_off[E_] = a;   // == TK_ always
    }
}

// ---------------- compact staged lists into flat slot space ----------------
__global__ void compact_kernel() {
    int e = blockIdx.y;
    int i = blockIdx.x*256 + threadIdx.x;
    if (i < g_cnt[e]) {
        int slot = g_off[e] + i;
        int tok = g_tok2d[e*T_ + i];
        g_tokslot[slot] = tok;
        g_wslot[slot]   = g_w2d[e*T_ + i];
        int c = atomicAdd(&g_tokc[tok], 1);
        g_slot_of[tok*KTOP + c] = slot;
    }
}

// ---------------- generic TN GEMM: C[M,N] = epi(A[M,K] @ W[N,K]^T) ----------------
// EPI: 0 = store, 1 = silu->store, 2 = C *= result, 3 = rowscale[r]*result -> store
#define BM 128
#define BN 128
#define BKK 16

__device__ __forceinline__ float epi_silu(float v) { return v / (1.f + expf(-v)); }

template<int EPI>
__global__ __launch_bounds__(256, 2)
void gemm_tn(const float* __restrict__ A, int lda,
             const float* __restrict__ W, size_t wstride,
             float* __restrict__ C, int ldc,
             int M, int N, int Kd,
             const int* __restrict__ off,
             const int* __restrict__ rowmap,
             const float* __restrict__ rowscale)
{
    int e = blockIdx.z;
    int rs, re;
    if (off) { rs = off[e]; re = off[e+1]; } else { rs = 0; re = M; }
    int row0 = rs + blockIdx.x * BM;
    if (row0 >= re) return;
    int col0 = blockIdx.y * BN;
    const float* Wb = W + (size_t)e * wstride;

    __shared__ float As[BKK][BM];
    __shared__ float Bs[BKK][BN];

    int tid = threadIdx.x;
    int tx = tid & 15, ty = tid >> 4;

    float acc[8][8];
    #pragma unroll
    for (int i = 0; i < 8; i++)
        #pragma unroll
        for (int j = 0; j < 8; j++) acc[i][j] = 0.f;

    for (int k0 = 0; k0 < Kd; k0 += BKK) {
        #pragma unroll
        for (int li = 0; li < 2; li++) {
            int idx = tid + li*256;
            int m = idx >> 2, kv = (idx & 3) * 4;
            int r = row0 + m;
            float4 v = make_float4(0.f,0.f,0.f,0.f);
            if (r < re) {
                int ar = rowmap ? rowmap[r] : r;
                v = *reinterpret_cast<const float4*>(A + (size_t)ar*lda + k0 + kv);
            }
            As[kv+0][m] = v.x; As[kv+1][m] = v.y; As[kv+2][m] = v.z; As[kv+3][m] = v.w;
        }
        #pragma unroll
        for (int li = 0; li < 2; li++) {
            int idx = tid + li*256;
            int n = idx >> 2, kv = (idx & 3) * 4;
            float4 v = *reinterpret_cast<const float4*>(Wb + (size_t)(col0 + n)*Kd + k0 + kv);
            Bs[kv+0][n] = v.x; Bs[kv+1][n] = v.y; Bs[kv+2][n] = v.z; Bs[kv+3][n] = v.w;
        }
        __syncthreads();
        #pragma unroll
        for (int k = 0; k < BKK; k++) {
            float a[8], b[8];
            *reinterpret_cast<float4*>(&a[0]) = *reinterpret_cast<const float4*>(&As[k][ty*8]);
            *reinterpret_cast<float4*>(&a[4]) = *reinterpret_cast<const float4*>(&As[k][ty*8+4]);
            *reinterpret_cast<float4*>(&b[0]) = *reinterpret_cast<const float4*>(&Bs[k][tx*8]);
            *reinterpret_cast<float4*>(&b[4]) = *reinterpret_cast<const float4*>(&Bs[k][tx*8+4]);
            #pragma unroll
            for (int i = 0; i < 8; i++)
                #pragma unroll
                for (int j = 0; j < 8; j++)
                    acc[i][j] = fmaf(a[i], b[j], acc[i][j]);
        }
        __syncthreads();
    }

    #pragma unroll
    for (int i = 0; i < 8; i++) {
        int r = row0 + ty*8 + i;
        if (r >= re) continue;
        float rsc = 1.f;
        if (EPI == 3) rsc = rowscale[r];
        float* Crow = C + (size_t)r*ldc + col0 + tx*8;
        #pragma unroll
        for (int jv = 0; jv < 2; jv++) {
            float4 v;
            v.x = acc[i][jv*4+0]; v.y = acc[i][jv*4+1];
            v.z = acc[i][jv*4+2]; v.w = acc[i][jv*4+3];
            if (EPI == 1) { v.x = epi_silu(v.x); v.y = epi_silu(v.y); v.z = epi_silu(v.z); v.w = epi_silu(v.w); }
            if (EPI == 3) { v.x *= rsc; v.y *= rsc; v.z *= rsc; v.w *= rsc; }
            if (EPI == 2) {
                float4 o = *reinterpret_cast<float4*>(Crow + jv*4);
                v.x *= o.x; v.y *= o.y; v.z *= o.z; v.w *= o.w;
            }
            *reinterpret_cast<float4*>(Crow + jv*4) = v;
        }
    }
}

// ---------------- final combine: out[t] = shared[t] + sum_k eout[slot(t,k)] ----------------
__global__ void combine_kernel(float* __restrict__ out) {
    int t = blockIdx.x;
    int c = blockIdx.y*256 + threadIdx.x;
    float s = out[(size_t)t*H_ + c];   // shared-expert result already stored
    #pragma unroll
    for (int k = 0; k < KTOP; k++) {
        int slot = g_slot_of[t*KTOP + k];
        s += g_eout[(size_t)slot*H_ + c];
    }
    out[(size_t)t*H_ + c] = s;
}

// ---------------- host side ----------------
template<typename Tp>
static Tp* sym(const void* s) {
    void* p = nullptr;
    cudaGetSymbolAddress(&p, s);
    return (Tp*)p;
}

static void launch_gemm(int epi, dim3 grid,
                        const float* A, int lda,
                        const float* W, size_t ws,
                        float* C, int ldc,
                        int M, int N, int Kd,
                        const int* off, const int* rowmap, const float* rowscale)
{
    switch (epi) {
        case 0: gemm_tn<0><<<grid,256>>>(A,lda,W,ws,C,ldc,M,N,Kd,off,rowmap,rowscale); break;
        case 1: gemm_tn<1><<<grid,256>>>(A,lda,W,ws,C,ldc,M,N,Kd,off,rowmap,rowscale); break;
        case 2: gemm_tn<2><<<grid,256>>>(A,lda,W,ws,C,ldc,M,N,Kd,off,rowmap,rowscale); break;
        case 3: gemm_tn<3><<<grid,256>>>(A,lda,W,ws,C,ldc,M,N,Kd,off,rowmap,rowscale); break;
    }
}

extern "C" void kernel_launch(void* const* d_in, const int* in_sizes, int n_in,
                              void* d_out, int out_size)
{
    const float* x      = (const float*)d_in[0];
    const float* gate_w = (const float*)d_in[1];
    const float* Rg     = (const float*)d_in[2];
    const float* Ru     = (const float*)d_in[3];
    const float* Rd     = (const float*)d_in[4];
    const float* Ug     = (const float*)d_in[5];
    const float* Cg     = (const float*)d_in[6];
    const float* Uu     = (const float*)d_in[7];
    const float* Cu     = (const float*)d_in[8];
    const float* Ud     = (const float*)d_in[9];
    const float* Cd     = (const float*)d_in[10];
    const float* s_Rg   = (const float*)d_in[11];
    const float* s_Ug   = (const float*)d_in[12];
    const float* s_Cg   = (const float*)d_in[13];
    const float* s_Ru   = (const float*)d_in[14];
    const float* s_Uu   = (const float*)d_in[15];
    const float* s_Cu   = (const float*)d_in[16];
    const float* s_Rd   = (const float*)d_in[17];
    const float* s_Ud   = (const float*)d_in[18];
    const float* s_Cd   = (const float*)d_in[19];
    float* out = (float*)d_out;

    float* p_rg   = sym<float>(g_rg);
    float* p_ru   = sym<float>(g_ru);
    float* p_srg  = sym<float>(g_srg);
    float* p_sru  = sym<float>(g_sru);
    float* p_tg   = sym<float>(g_tg);
    float* p_tu   = sym<float>(g_tu);
    float* p_h    = sym<float>(g_h);
    float* p_rd   = sym<float>(g_rd);
    float* p_td   = sym<float>(g_td);
    float* p_sh   = sym<float>(g_sh);
    float* p_st1  = sym<float>(g_st1);
    float* p_st2  = sym<float>(g_st2);
    float* p_srd  = sym<float>(g_srd);
    float* p_std  = sym<float>(g_std);
    float* p_eout = sym<float>(g_eout);
    int*   p_off  = sym<int>(g_off);
    int*   p_map  = sym<int>(g_tokslot);
    float* p_ws   = sym<float>(g_wslot);

    // routing
    init_kernel<<<16,256>>>();
    gate_kernel<<<T_,256>>>(x, gate_w);
    scan_kernel<<<1,32>>>();
    compact_kernel<<<dim3(16,E_),256>>>();

    // rank projections (expert-shared and shared-expert): [T,2048] -> [T,128]
    launch_gemm(0, dim3(32,1,1), x,H_, Rg,  0, p_rg, R_, T_,R_,H_, nullptr,nullptr,nullptr);
    launch_gemm(0, dim3(32,1,1), x,H_, Ru,  0, p_ru, R_, T_,R_,H_, nullptr,nullptr,nullptr);
    launch_gemm(0, dim3(32,1,1), x,H_, s_Rg,0, p_srg,R_, T_,R_,H_, nullptr,nullptr,nullptr);
    launch_gemm(0, dim3(32,1,1), x,H_, s_Ru,0, p_sru,R_, T_,R_,H_, nullptr,nullptr,nullptr);

    // per-expert chain over flat slots (gather rg/ru rows by token)
    launch_gemm(0, dim3(32,1,E_),  p_rg,R_, Ug,(size_t)R_*R_, p_tg,R_, 0,R_,R_, p_off,p_map,nullptr);
    launch_gemm(0, dim3(32,1,E_),  p_ru,R_, Uu,(size_t)R_*R_, p_tu,R_, 0,R_,R_, p_off,p_map,nullptr);
    launch_gemm(1, dim3(32,11,E_), p_tg,R_, Cg,(size_t)I_*R_, p_h, I_, 0,I_,R_, p_off,nullptr,nullptr); // h = silu(tg@Cg^T)
    launch_gemm(2, dim3(32,11,E_), p_tu,R_, Cu,(size_t)I_*R_, p_h, I_, 0,I_,R_, p_off,nullptr,nullptr); // h *= tu@Cu^T
    launch_gemm(0, dim3(128,1,1),  p_h, I_, Rd,0,             p_rd,R_, TK_,R_,I_, nullptr,nullptr,nullptr);
    launch_gemm(0, dim3(32,1,E_),  p_rd,R_, Ud,(size_t)R_*R_, p_td,R_, 0,R_,R_, p_off,nullptr,nullptr);
    launch_gemm(3, dim3(32,16,E_), p_td,R_, Cd,(size_t)H_*R_, p_eout,H_, 0,H_,R_, p_off,nullptr,p_ws);  // w*(td@Cd^T)

    // shared expert chain
    launch_gemm(0, dim3(32,1,1),  p_srg,R_,  s_Ug,0, p_st1,R_, T_,R_,R_,  nullptr,nullptr,nullptr);
    launch_gemm(1, dim3(32,22,1), p_st1,R_,  s_Cg,0, p_sh,SI_, T_,SI_,R_, nullptr,nullptr,nullptr);
    launch_gemm(0, dim3(32,1,1),  p_sru,R_,  s_Uu,0, p_st2,R_, T_,R_,R_,  nullptr,nullptr,nullptr);
    launch_gemm(2, dim3(32,22,1), p_st2,R_,  s_Cu,0, p_sh,SI_, T_,SI_,R_, nullptr,nullptr,nullptr);
    launch_gemm(0, dim3(32,1,1),  p_sh,SI_,  s_Rd,0, p_srd,R_, T_,R_,SI_, nullptr,nullptr,nullptr);
    launch_gemm(0, dim3(32,1,1),  p_srd,R_,  s_Ud,0, p_std,R_, T_,R_,R_,  nullptr,nullptr,nullptr);
    launch_gemm(0, dim3(32,16,1), p_std,R_,  s_Cd,0, out,H_,   T_,H_,R_,  nullptr,nullptr,nullptr);    // writes full d_out

    // out[t] = shared[t] + sum of this token's 4 expert-slot rows
    combine_kernel<<<dim3(T_,H_/256),256>>>(out);
}

// round 3
// speedup vs baseline: 2.3302x; 2.3302x over previous
#include <cuda_runtime.h>
#include <math.h>
#include <stdint.h>

#define T_   4096
#define H_   2048
#define E_   32
#define KTOP 4
#define I_   1408
#define R_   128
#define SI_  2816
#define TK_  (T_*KTOP)

// ---------------- scratch (device globals; no allocation allowed) ----------------
__device__ int   g_cnt[E_];
__device__ int   g_off[E_+1];
__device__ int   g_tok2d[E_*T_];
__device__ float g_w2d[E_*T_];
__device__ int   g_tokslot[TK_];
__device__ float g_wslot[TK_];
__device__ int   g_slot_of[TK_];
__device__ int   g_tokc[T_];
__device__ float g_rg[T_*R_];
__device__ float g_ru[T_*R_];
__device__ float g_srg[T_*R_];
__device__ float g_sru[T_*R_];
__device__ float g_tg[TK_*R_];
__device__ float g_tu[TK_*R_];
__device__ float g_h[(size_t)TK_*I_];
__device__ float g_rd[TK_*R_];
__device__ float g_td[TK_*R_];
__device__ float g_sh[(size_t)T_*SI_];
__device__ float g_st1[T_*R_];
__device__ float g_st2[T_*R_];
__device__ float g_srd[T_*R_];
__device__ float g_std[T_*R_];
__device__ float g_eout[(size_t)TK_*H_];

// ---------------- init ----------------
__global__ void init_kernel() {
    int i = blockIdx.x*256 + threadIdx.x;
    if (i < E_) g_cnt[i] = 0;
    if (i < T_) g_tokc[i] = 0;
}

// ---------------- gate: fp32 logits, softmax, top-4 (fp32 kept: routing-critical) ----------------
__global__ void gate_kernel(const float* __restrict__ x, const float* __restrict__ gw) {
    __shared__ float xs[H_];
    __shared__ float lg[E_];
    int t = blockIdx.x;
    const float* xr = x + (size_t)t*H_;
    for (int i = threadIdx.x; i < H_; i += 256) xs[i] = xr[i];
    __syncthreads();
    int warp = threadIdx.x >> 5, lane = threadIdx.x & 31;
    for (int e = warp; e < E_; e += 8) {
        const float* w = gw + (size_t)e*H_;
        float s = 0.f;
        for (int i = lane; i < H_; i += 32) s += xs[i]*w[i];
        #pragma unroll
        for (int o = 16; o; o >>= 1) s += __shfl_xor_sync(0xffffffffu, s, o);
        if (lane == 0) lg[e] = s;
    }
    __syncthreads();
    if (threadIdx.x == 0) {
        float mx = lg[0];
        for (int e = 1; e < E_; e++) mx = fmaxf(mx, lg[e]);
        float p[E_]; float sum = 0.f;
        for (int e = 0; e < E_; e++) { p[e] = expf(lg[e]-mx); sum += p[e]; }
        float inv = 1.f/sum;
        bool taken[E_];
        for (int e = 0; e < E_; e++) taken[e] = false;
        int idx[KTOP]; float w4[KTOP]; float ws = 0.f;
        for (int k = 0; k < KTOP; k++) {
            int best = 0; float bv = -1.f;
            for (int e = 0; e < E_; e++)
                if (!taken[e] && p[e] > bv) { bv = p[e]; best = e; }
            taken[best] = true; idx[k] = best; w4[k] = bv*inv; ws += w4[k];
        }
        float rn = 1.f/(ws + 1e-20f);
        for (int k = 0; k < KTOP; k++) {
            int e = idx[k];
            int pos = atomicAdd(&g_cnt[e], 1);
            g_tok2d[e*T_ + pos] = t;
            g_w2d [e*T_ + pos] = w4[k]*rn;
        }
    }
}

__global__ void scan_kernel() {
    if (threadIdx.x == 0 && blockIdx.x == 0) {
        int a = 0;
        for (int e = 0; e < E_; e++) { g_off[e] = a; a += g_cnt[e]; }
        g_off[E_] = a;
    }
}

__global__ void compact_kernel() {
    int e = blockIdx.y;
    int i = blockIdx.x*256 + threadIdx.x;
    if (i < g_cnt[e]) {
        int slot = g_off[e] + i;
        int tok = g_tok2d[e*T_ + i];
        g_tokslot[slot] = tok;
        g_wslot[slot]   = g_w2d[e*T_ + i];
        int c = atomicAdd(&g_tokc[tok], 1);
        g_slot_of[tok*KTOP + c] = slot;
    }
}

// ---------------- TF32 tensor-core TN GEMM ----------------
// C[M,N] = epi(A[M,K] @ W[N,K]^T)
// EPI: 0 store, 1 silu, 2 C*=res, 3 rowscale*res
// Tile 128x128x32, 8 warps (4 m x 2 n), each warp 32x64 via m16n8k8.

__device__ __forceinline__ uint32_t f2tf32(float f) {
    uint32_t r; asm("cvt.rna.tf32.f32 %0, %1;" : "=r"(r) : "f"(f)); return r;
}

__device__ __forceinline__ void mma_tf32(float* d, const uint32_t* a, const uint32_t* b) {
    asm volatile(
        "mma.sync.aligned.m16n8k8.row.col.f32.tf32.tf32.f32 "
        "{%0,%1,%2,%3},{%4,%5,%6,%7},{%8,%9},{%0,%1,%2,%3};\n"
        : "+f"(d[0]), "+f"(d[1]), "+f"(d[2]), "+f"(d[3])
        : "r"(a[0]), "r"(a[1]), "r"(a[2]), "r"(a[3]), "r"(b[0]), "r"(b[1]));
}

__device__ __forceinline__ float epi_silu(float v) { return v / (1.f + expf(-v)); }

#define LDSA 36   // row stride in words: bank = (4m + k) % 32 -> conflict-free frags

template<int EPI>
__global__ __launch_bounds__(256)
void gemm_tf32(const float* __restrict__ A, int lda,
               const float* __restrict__ W, size_t wstride,
               float* __restrict__ C, int ldc,
               int M, int N, int Kd,
               const int* __restrict__ off,
               const int* __restrict__ rowmap,
               const float* __restrict__ rowscale)
{
    int e = blockIdx.z;
    int rs, re;
    if (off) { rs = off[e]; re = off[e+1]; } else { rs = 0; re = M; }
    int row0 = rs + blockIdx.x * 128;
    if (row0 >= re) return;
    int col0 = blockIdx.y * 128;
    const float* Wb = W + (size_t)e * wstride;

    __shared__ uint32_t As[128][LDSA];
    __shared__ uint32_t Bs[128][LDSA];

    int tid  = threadIdx.x;
    int wid  = tid >> 5, lane = tid & 31;
    int g    = lane >> 2, t = lane & 3;
    int wm   = wid & 3;        // warp row (32 rows each)
    int wn   = wid >> 2;       // warp col (64 cols each)

    float acc[2][8][4];
    #pragma unroll
    for (int a0 = 0; a0 < 2; a0++)
        #pragma unroll
        for (int b0 = 0; b0 < 8; b0++)
            #pragma unroll
            for (int c0 = 0; c0 < 4; c0++) acc[a0][b0][c0] = 0.f;

    for (int k0 = 0; k0 < Kd; k0 += 32) {
        // stage A tile (tf32-convert at store)
        #pragma unroll
        for (int it = 0; it < 4; it++) {
            int pos = tid + it*256;
            int m = pos >> 3, kq = (pos & 7) * 4;
            int r = row0 + m;
            float4 v = make_float4(0.f,0.f,0.f,0.f);
            if (r < re) {
                int ar = rowmap ? rowmap[r] : r;
                v = *reinterpret_cast<const float4*>(A + (size_t)ar*lda + k0 + kq);
            }
            uint4 u;
            u.x = f2tf32(v.x); u.y = f2tf32(v.y); u.z = f2tf32(v.z); u.w = f2tf32(v.w);
            *reinterpret_cast<uint4*>(&As[m][kq]) = u;
        }
        // stage B tile
        #pragma unroll
        for (int it = 0; it < 4; it++) {
            int pos = tid + it*256;
            int n = pos >> 3, kq = (pos & 7) * 4;
            float4 v = *reinterpret_cast<const float4*>(Wb + (size_t)(col0 + n)*Kd + k0 + kq);
            uint4 u;
            u.x = f2tf32(v.x); u.y = f2tf32(v.y); u.z = f2tf32(v.z); u.w = f2tf32(v.w);
            *reinterpret_cast<uint4*>(&Bs[n][kq]) = u;
        }
        __syncthreads();

        #pragma unroll
        for (int kk = 0; kk < 32; kk += 8) {
            uint32_t bf[8][2];
            #pragma unroll
            for (int nt = 0; nt < 8; nt++) {
                int nb = wn*64 + nt*8 + g;
                bf[nt][0] = Bs[nb][kk + t];
                bf[nt][1] = Bs[nb][kk + t + 4];
            }
            #pragma unroll
            for (int mt = 0; mt < 2; mt++) {
                int mb = wm*32 + mt*16;
                uint32_t af[4];
                af[0] = As[mb + g    ][kk + t    ];
                af[1] = As[mb + g + 8][kk + t    ];
                af[2] = As[mb + g    ][kk + t + 4];
                af[3] = As[mb + g + 8][kk + t + 4];
                #pragma unroll
                for (int nt = 0; nt < 8; nt++)
                    mma_tf32(acc[mt][nt], af, bf[nt]);
            }
        }
        __syncthreads();
    }

    // epilogue: d0,d1 at (g, 2t..2t+1); d2,d3 at (g+8, same cols)
    #pragma unroll
    for (int mt = 0; mt < 2; mt++) {
        #pragma unroll
        for (int half = 0; half < 2; half++) {
            int r = row0 + wm*32 + mt*16 + g + half*8;
            if (r >= re) continue;
            float rsc = (EPI == 3) ? rowscale[r] : 1.f;
            #pragma unroll
            for (int nt = 0; nt < 8; nt++) {
                int cix = col0 + wn*64 + nt*8 + 2*t;
                float v0 = acc[mt][nt][half*2 + 0];
                float v1 = acc[mt][nt][half*2 + 1];
                if (EPI == 1) { v0 = epi_silu(v0); v1 = epi_silu(v1); }
                if (EPI == 3) { v0 *= rsc; v1 *= rsc; }
                float* p = C + (size_t)r*ldc + cix;
                if (EPI == 2) {
                    float2 o = *reinterpret_cast<float2*>(p);
                    v0 *= o.x; v1 *= o.y;
                }
                float2 vv; vv.x = v0; vv.y = v1;
                *reinterpret_cast<float2*>(p) = vv;
            }
        }
    }
}

// ---------------- final combine ----------------
__global__ void combine_kernel(float* __restrict__ out) {
    int t = blockIdx.x;
    int c = blockIdx.y*256 + threadIdx.x;
    float s = out[(size_t)t*H_ + c];
    #pragma unroll
    for (int k = 0; k < KTOP; k++) {
        int slot = g_slot_of[t*KTOP + k];
        s += g_eout[(size_t)slot*H_ + c];
    }
    out[(size_t)t*H_ + c] = s;
}

// ---------------- host side ----------------
template<typename Tp>
static Tp* sym(const void* s) {
    void* p = nullptr;
    cudaGetSymbolAddress(&p, s);
    return (Tp*)p;
}

static void launch_gemm(int epi, dim3 grid,
                        const float* A, int lda,
                        const float* W, size_t ws,
                        float* C, int ldc,
                        int M, int N, int Kd,
                        const int* off, const int* rowmap, const float* rowscale)
{
    switch (epi) {
        case 0: gemm_tf32<0><<<grid,256>>>(A,lda,W,ws,C,ldc,M,N,Kd,off,rowmap,rowscale); break;
        case 1: gemm_tf32<1><<<grid,256>>>(A,lda,W,ws,C,ldc,M,N,Kd,off,rowmap,rowscale); break;
        case 2: gemm_tf32<2><<<grid,256>>>(A,lda,W,ws,C,ldc,M,N,Kd,off,rowmap,rowscale); break;
        case 3: gemm_tf32<3><<<grid,256>>>(A,lda,W,ws,C,ldc,M,N,Kd,off,rowmap,rowscale); break;
    }
}

extern "C" void kernel_launch(void* const* d_in, const int* in_sizes, int n_in,
                              void* d_out, int out_size)
{
    const float* x      = (const float*)d_in[0];
    const float* gate_w = (const float*)d_in[1];
    const float* Rg     = (const float*)d_in[2];
    const float* Ru     = (const float*)d_in[3];
    const float* Rd     = (const float*)d_in[4];
    const float* Ug     = (const float*)d_in[5];
    const float* Cg     = (const float*)d_in[6];
    const float* Uu     = (const float*)d_in[7];
    const float* Cu     = (const float*)d_in[8];
    const float* Ud     = (const float*)d_in[9];
    const float* Cd     = (const float*)d_in[10];
    const float* s_Rg   = (const float*)d_in[11];
    const float* s_Ug   = (const float*)d_in[12];
    const float* s_Cg   = (const float*)d_in[13];
    const float* s_Ru   = (const float*)d_in[14];
    const float* s_Uu   = (const float*)d_in[15];
    const float* s_Cu   = (const float*)d_in[16];
    const float* s_Rd   = (const float*)d_in[17];
    const float* s_Ud   = (const float*)d_in[18];
    const float* s_Cd   = (const float*)d_in[19];
    float* out = (float*)d_out;

    float* p_rg   = sym<float>(g_rg);
    float* p_ru   = sym<float>(g_ru);
    float* p_srg  = sym<float>(g_srg);
    float* p_sru  = sym<float>(g_sru);
    float* p_tg   = sym<float>(g_tg);
    float* p_tu   = sym<float>(g_tu);
    float* p_h    = sym<float>(g_h);
    float* p_rd   = sym<float>(g_rd);
    float* p_td   = sym<float>(g_td);
    float* p_sh   = sym<float>(g_sh);
    float* p_st1  = sym<float>(g_st1);
    float* p_st2  = sym<float>(g_st2);
    float* p_srd  = sym<float>(g_srd);
    float* p_std  = sym<float>(g_std);
    float* p_eout = sym<float>(g_eout);
    int*   p_off  = sym<int>(g_off);
    int*   p_map  = sym<int>(g_tokslot);
    float* p_ws   = sym<float>(g_wslot);

    // routing
    init_kernel<<<16,256>>>();
    gate_kernel<<<T_,256>>>(x, gate_w);
    scan_kernel<<<1,32>>>();
    compact_kernel<<<dim3(16,E_),256>>>();

    // rank projections: [T,2048] -> [T,128]
    launch_gemm(0, dim3(32,1,1), x,H_, Rg,  0, p_rg, R_, T_,R_,H_, nullptr,nullptr,nullptr);
    launch_gemm(0, dim3(32,1,1), x,H_, Ru,  0, p_ru, R_, T_,R_,H_, nullptr,nullptr,nullptr);
    launch_gemm(0, dim3(32,1,1), x,H_, s_Rg,0, p_srg,R_, T_,R_,H_, nullptr,nullptr,nullptr);
    launch_gemm(0, dim3(32,1,1), x,H_, s_Ru,0, p_sru,R_, T_,R_,H_, nullptr,nullptr,nullptr);

    // per-expert chain over flat slots
    launch_gemm(0, dim3(32,1,E_),  p_rg,R_, Ug,(size_t)R_*R_, p_tg,R_, 0,R_,R_, p_off,p_map,nullptr);
    launch_gemm(0, dim3(32,1,E_),  p_ru,R_, Uu,(size_t)R_*R_, p_tu,R_, 0,R_,R_, p_off,p_map,nullptr);
    launch_gemm(1, dim3(32,11,E_), p_tg,R_, Cg,(size_t)I_*R_, p_h, I_, 0,I_,R_, p_off,nullptr,nullptr);
    launch_gemm(2, dim3(32,11,E_), p_tu,R_, Cu,(size_t)I_*R_, p_h, I_, 0,I_,R_, p_off,nullptr,nullptr);
    launch_gemm(0, dim3(128,1,1),  p_h, I_, Rd,0,             p_rd,R_, TK_,R_,I_, nullptr,nullptr,nullptr);
    launch_gemm(0, dim3(32,1,E_),  p_rd,R_, Ud,(size_t)R_*R_, p_td,R_, 0,R_,R_, p_off,nullptr,nullptr);
    launch_gemm(3, dim3(32,16,E_), p_td,R_, Cd,(size_t)H_*R_, p_eout,H_, 0,H_,R_, p_off,nullptr,p_ws);

    // shared expert chain
    launch_gemm(0, dim3(32,1,1),  p_srg,R_,  s_Ug,0, p_st1,R_, T_,R_,R_,  nullptr,nullptr,nullptr);
    launch_gemm(1, dim3(32,22,1), p_st1,R_,  s_Cg,0, p_sh,SI_, T_,SI_,R_, nullptr,nullptr,nullptr);
    launch_gemm(0, dim3(32,1,1),  p_sru,R_,  s_Uu,0, p_st2,R_, T_,R_,R_,  nullptr,nullptr,nullptr);
    launch_gemm(2, dim3(32,22,1), p_st2,R_,  s_Cu,0, p_sh,SI_, T_,SI_,R_, nullptr,nullptr,nullptr);
    launch_gemm(0, dim3(32,1,1),  p_sh,SI_,  s_Rd,0, p_srd,R_, T_,R_,SI_, nullptr,nullptr,nullptr);
    launch_gemm(0, dim3(32,1,1),  p_srd,R_,  s_Ud,0, p_std,R_, T_,R_,R_,  nullptr,nullptr,nullptr);
    launch_gemm(0, dim3(32,16,1), p_std,R_,  s_Cd,0, out,H_,   T_,H_,R_,  nullptr,nullptr,nullptr);

    combine_kernel<<<dim3(T_,H_/256),256>>>(out);
}